// round 8
// baseline (speedup 1.0000x reference)
#include <cuda_runtime.h>

// GRU_8211977470410 — bidirectional GRU (H=32, in=1), B=2048, T=512, MLP head.
// Backward direction collapses to ONE step (scan reverse=True: ys_b[-1] = GRU(0, x[T-1])).
//
// R7 = R5 resubmit (infra failure last round, kernel never executed).
// 1 batch per warp, 2048 warps (1024 blocks x 64 thr), single wave,
// 3.46 warps/SMSP for latency hiding (R4 showed issue=48% latency-bound at 1.73).
// lane = hidden unit; W_hh rows in regs as f32x2 with exp2-scales PRE-FOLDED
// (r,z rows scaled by -log2e; n row by 2*log2e) so MUFU args need no scaling mul.
// h is NOT register-resident: reloaded from smem each step (reg budget 144).

#define HDIM 32
#define FULLMASK 0xffffffffu
typedef unsigned long long u64;

__device__ __forceinline__ u64 pack2(float lo, float hi) {
    u64 d; asm("mov.b64 %0, {%1, %2};" : "=l"(d) : "f"(lo), "f"(hi)); return d;
}
__device__ __forceinline__ void unpack2(u64 v, float& lo, float& hi) {
    asm("mov.b64 {%0, %1}, %2;" : "=f"(lo), "=f"(hi) : "l"(v));
}
__device__ __forceinline__ u64 ffma2(u64 a, u64 b, u64 c) {
    u64 d; asm("fma.rn.f32x2 %0, %1, %2, %3;" : "=l"(d) : "l"(a), "l"(b), "l"(c)); return d;
}
__device__ __forceinline__ u64 fadd2(u64 a, u64 b) {
    u64 d; asm("add.rn.f32x2 %0, %1, %2;" : "=l"(d) : "l"(a), "l"(b)); return d;
}
__device__ __forceinline__ float ex2f(float x) {
    float r; asm("ex2.approx.f32 %0, %1;" : "=f"(r) : "f"(x)); return r;
}
__device__ __forceinline__ float rcpf(float x) {
    float r; asm("rcp.approx.f32 %0, %1;" : "=f"(r) : "f"(x)); return r;
}
__device__ __forceinline__ float sigm(float x) {
    return __fdividef(1.0f, 1.0f + __expf(-x));
}
__device__ __forceinline__ float tanh_fast(float x) {
    float e = __expf(2.0f * x);
    return 1.0f - __fdividef(2.0f, e + 1.0f);
}

__global__ void __launch_bounds__(64, 7)
gru_bidir_kernel(const float* __restrict__ x,
                 const float* __restrict__ Wih_f, const float* __restrict__ Whh_f,
                 const float* __restrict__ bih_f, const float* __restrict__ bhh_f,
                 const float* __restrict__ Wih_b, const float* __restrict__ bih_b,
                 const float* __restrict__ bhh_b,
                 const float* __restrict__ W1, const float* __restrict__ b1v,
                 const float* __restrict__ W2, const float* __restrict__ b2v,
                 float* __restrict__ out, int B, int T)
{
    __shared__ __align__(16) float xch[2][2][32];   // [warp][parity][lane] h exchange
    __shared__ __align__(16) float scr[2][80];      // [warp] head scratch: concat(64)+h1(16)

    const int lane = threadIdx.x & 31;
    const int warp = threadIdx.x >> 5;
    int b = blockIdx.x * 2 + warp;
    const bool valid = (b < B);
    if (!valid) b = B - 1;

    const int rr = lane, rz = lane + HDIM, rn = lane + 2 * HDIM;

    const float L2E  = 1.4426950408889634f;
    const float NL2E = -L2E;          // sigmoid:  s(a) = 1/(1+2^(-L2E*a))
    const float TL2E = 2.0f * L2E;    // tanh:     t(u) = 1 - 2/(2^(2*L2E*u)+1)

    // ---- W_hh rows (r,z,n for this lane) as f32x2, exp2-scales folded in ----
    u64 wr[16], wz[16], wn[16];
    {
        const float4* pr = reinterpret_cast<const float4*>(Whh_f + rr * HDIM);
        const float4* pz = reinterpret_cast<const float4*>(Whh_f + rz * HDIM);
        const float4* pn = reinterpret_cast<const float4*>(Whh_f + rn * HDIM);
#pragma unroll
        for (int i = 0; i < 8; i++) {
            float4 a = pr[i];
            wr[2*i]   = pack2(NL2E*a.x, NL2E*a.y);
            wr[2*i+1] = pack2(NL2E*a.z, NL2E*a.w);
            float4 c = pz[i];
            wz[2*i]   = pack2(NL2E*c.x, NL2E*c.y);
            wz[2*i+1] = pack2(NL2E*c.z, NL2E*c.w);
            float4 d = pn[i];
            wn[2*i]   = pack2(TL2E*d.x, TL2E*d.y);
            wn[2*i+1] = pack2(TL2E*d.z, TL2E*d.w);
        }
    }
    // scaled input weights / biases (b_ih folded into matvec accumulator init)
    const u64 wrz2 = pack2(NL2E * Wih_f[rr], NL2E * Wih_f[rz]);
    const float winS = TL2E * Wih_f[rn];
    const float binS = TL2E * bih_f[rn];
    const u64 accR0 = pack2(NL2E * (bhh_f[rr] + bih_f[rr]), 0.0f);
    const u64 accZ0 = pack2(NL2E * (bhh_f[rz] + bih_f[rz]), 0.0f);
    const u64 accN0 = pack2(TL2E * bhh_f[rn], 0.0f);
    const u64 one2  = pack2(1.0f, 1.0f);

    const float* xW = x + (size_t)b * T;

    // init h = 0 in exchange buffer parity 0
    xch[warp][0][lane] = 0.0f;
    __syncwarp();

    float hs = 0.0f;   // this lane's own hidden value

    auto step = [&](float xv, int rp) {
        const ulonglong2* q = reinterpret_cast<const ulonglong2*>(xch[warp][rp]);
        // ---- matvec: 6 independent 8-deep FFMA2 chains, h loaded inline ----
        u64 aR0 = accR0, aR1 = 0ull;
        u64 aZ0 = accZ0, aZ1 = 0ull;
        u64 aN0 = accN0, aN1 = 0ull;
#pragma unroll
        for (int j = 0; j < 4; j++) {
            ulonglong2 hA = q[j];        // h pairs 2j, 2j+1
            ulonglong2 hB = q[j + 4];    // h pairs 2j+8, 2j+9
            aR0 = ffma2(wr[2*j],   hA.x, aR0);  aR0 = ffma2(wr[2*j+1], hA.y, aR0);
            aR1 = ffma2(wr[2*j+8], hB.x, aR1);  aR1 = ffma2(wr[2*j+9], hB.y, aR1);
            aZ0 = ffma2(wz[2*j],   hA.x, aZ0);  aZ0 = ffma2(wz[2*j+1], hA.y, aZ0);
            aZ1 = ffma2(wz[2*j+8], hB.x, aZ1);  aZ1 = ffma2(wz[2*j+9], hB.y, aZ1);
            aN0 = ffma2(wn[2*j],   hA.x, aN0);  aN0 = ffma2(wn[2*j+1], hA.y, aN0);
            aN1 = ffma2(wn[2*j+8], hB.x, aN1);  aN1 = ffma2(wn[2*j+9], hB.y, aN1);
        }
        float lo, hi; u64 s;
        s = fadd2(aR0, aR1); unpack2(s, lo, hi); const float hr = lo + hi; // = -L2E*(Wr.h + br)
        s = fadd2(aZ0, aZ1); unpack2(s, lo, hi); const float hz = lo + hi;
        s = fadd2(aN0, aN1); unpack2(s, lo, hi); const float hn = lo + hi; // = 2L2E*(Wn.h + bhn)

        // r,z = sigmoid: already scaled, one packed ffma2 then ex2/rcp
        u64 pre = ffma2(pack2(xv, xv), wrz2, pack2(hr, hz));
        unpack2(pre, lo, hi);
        u64 d_ = fadd2(pack2(ex2f(lo), ex2f(hi)), one2);
        unpack2(d_, lo, hi);
        const float r = rcpf(lo);
        const float z = rcpf(hi);
        // n = tanh(u), arg pre-scaled by 2*L2E
        const float e = ex2f(fmaf(r, hn, fmaf(xv, winS, binS)));
        const float n = fmaf(-2.0f, rcpf(e + 1.0f), 1.0f);
        // h = z*(h - n) + n
        hs = fmaf(z, hs - n, n);

        xch[warp][rp ^ 1][lane] = hs;
        __syncwarp();
    };

    // ---- main scan, 4 steps/iter, float4 x prefetch (parity pattern 0,1,0,1) ----
    const float4* x4 = reinterpret_cast<const float4*>(xW);
    const int nIt = T >> 2;
    float4 c = x4[0];
    for (int it = 0; it < nIt; ++it) {
        int nx = (it + 1 < nIt) ? it + 1 : it;
        float4 nxt = x4[nx];
        step(c.x, 0);
        step(c.y, 1);
        step(c.z, 0);
        step(c.w, 1);
        c = nxt;
    }
    for (int t = nIt << 2; t < T; ++t) step(xW[t], t & 1);   // T%4 remainder

    // ---- backward direction: ONE step from h=0 on x[T-1] (W_hh_b unused) ----
    const float xl = xW[T - 1];
    const float rb = sigm(fmaf(xl, Wih_b[rr], bih_b[rr]) + bhh_b[rr]);
    const float zb = sigm(fmaf(xl, Wih_b[rz], bih_b[rz]) + bhh_b[rz]);
    const float nb = tanh_fast(fmaf(rb, bhh_b[rn], fmaf(xl, Wih_b[rn], bih_b[rn])));
    const float hb = (1.0f - zb) * nb;

    // ---- MLP head (per warp, own scratch) ----
    float* sc = scr[warp];
    sc[lane] = hs;
    sc[32 + lane] = hb;
    __syncwarp();

    if (lane < 16) {
        const float4* w4 = reinterpret_cast<const float4*>(W1 + lane * 64);
        float a = b1v[lane];
#pragma unroll
        for (int i = 0; i < 16; i++) {
            float4 w = w4[i];
            a = fmaf(w.x, sc[4*i],   a);
            a = fmaf(w.y, sc[4*i+1], a);
            a = fmaf(w.z, sc[4*i+2], a);
            a = fmaf(w.w, sc[4*i+3], a);
        }
        sc[64 + lane] = fmaxf(a, 0.0f);
    }
    __syncwarp();

    float v = (lane < 16) ? W2[lane] * sc[64 + lane] : 0.0f;
#pragma unroll
    for (int o = 16; o > 0; o >>= 1) v += __shfl_xor_sync(FULLMASK, v, o);

    if (lane == 0 && valid) out[b] = sigm(v + b2v[0]);
}

extern "C" void kernel_launch(void* const* d_in, const int* in_sizes, int n_in,
                              void* d_out, int out_size) {
    const float* x     = (const float*)d_in[0];
    const float* Wih_f = (const float*)d_in[1];
    const float* Whh_f = (const float*)d_in[2];
    const float* bih_f = (const float*)d_in[3];
    const float* bhh_f = (const float*)d_in[4];
    const float* Wih_b = (const float*)d_in[5];
    // d_in[6] = W_hh_b: mathematically unused (backward output at T-1 starts from h=0)
    const float* bih_b = (const float*)d_in[7];
    const float* bhh_b = (const float*)d_in[8];
    const float* W1    = (const float*)d_in[9];
    const float* b1v   = (const float*)d_in[10];
    const float* W2    = (const float*)d_in[11];
    const float* b2v   = (const float*)d_in[12];

    int B = out_size;                // output [B,1] fp32
    int T = in_sizes[0] / B;         // x is [B,T,1]

    int grid = (B + 1) / 2;          // 2 warps/block, 1 batch per warp
    gru_bidir_kernel<<<grid, 64>>>(x, Wih_f, Whh_f, bih_f, bhh_f,
                                   Wih_b, bih_b, bhh_b,
                                   W1, b1v, W2, b2v,
                                   (float*)d_out, B, T);
}

// round 9
// speedup vs baseline: 1.1830x; 1.1830x over previous
#include <cuda_runtime.h>
#include <cuda_fp16.h>

// GRU_8211977470410 — bidirectional GRU (H=32, in=1), B=2048, T=512, MLP head.
// Backward direction collapses to ONE step (scan reverse=True: ys_b[-1] = GRU(0, x[T-1])).
//
// R8: fp16 hidden matvec via HFMA2.
// Evidence: R3/R4/R7 wall time invariant under warp-count doubling and
// per-warp work halving => fma pipe saturated; fma.rn.f32x2 takes 2 issue
// slots (64-bit operands) => no gain over scalar FFMA. HFMA2 (fp16x2, 32-bit
// operands, rt=2) is the only true 2x-MAC lever on this pipe.
// W_hh rows -> fp16x2 with exp2 scales folded (r,z: -log2e; n: 2*log2e).
// Two 8-deep fp16 chains per gate + HADD2; cross-chain combine, biases and
// all gate math in fp32. h exchanged through smem as fp16 (4x LDS.128).

#define HDIM 32
#define FULLMASK 0xffffffffu
typedef unsigned long long u64;

__device__ __forceinline__ u64 pack2(float lo, float hi) {
    u64 d; asm("mov.b64 %0, {%1, %2};" : "=l"(d) : "f"(lo), "f"(hi)); return d;
}
__device__ __forceinline__ void unpack2(u64 v, float& lo, float& hi) {
    asm("mov.b64 {%0, %1}, %2;" : "=f"(lo), "=f"(hi) : "l"(v));
}
__device__ __forceinline__ u64 ffma2(u64 a, u64 b, u64 c) {
    u64 d; asm("fma.rn.f32x2 %0, %1, %2, %3;" : "=l"(d) : "l"(a), "l"(b), "l"(c)); return d;
}
__device__ __forceinline__ u64 fadd2(u64 a, u64 b) {
    u64 d; asm("add.rn.f32x2 %0, %1, %2;" : "=l"(d) : "l"(a), "l"(b)); return d;
}
__device__ __forceinline__ float ex2f(float x) {
    float r; asm("ex2.approx.f32 %0, %1;" : "=f"(r) : "f"(x)); return r;
}
__device__ __forceinline__ float rcpf(float x) {
    float r; asm("rcp.approx.f32 %0, %1;" : "=f"(r) : "f"(x)); return r;
}
__device__ __forceinline__ float sigm(float x) {
    return __fdividef(1.0f, 1.0f + __expf(-x));
}
__device__ __forceinline__ float tanh_fast(float x) {
    float e = __expf(2.0f * x);
    return 1.0f - __fdividef(2.0f, e + 1.0f);
}
__device__ __forceinline__ __half2 u2h(unsigned v) {
    union { unsigned u; __half2 h; } c; c.u = v; return c.h;
}

__global__ void __launch_bounds__(64)
gru_bidir_kernel(const float* __restrict__ x,
                 const float* __restrict__ Wih_f, const float* __restrict__ Whh_f,
                 const float* __restrict__ bih_f, const float* __restrict__ bhh_f,
                 const float* __restrict__ Wih_b, const float* __restrict__ bih_b,
                 const float* __restrict__ bhh_b,
                 const float* __restrict__ W1, const float* __restrict__ b1v,
                 const float* __restrict__ W2, const float* __restrict__ b2v,
                 float* __restrict__ out, int B, int T)
{
    __shared__ __align__(16) __half2 xchh[2][2][16];  // [warp][parity][pair] h exchange, fp16
    __shared__ __align__(16) float scr[2][80];        // [warp] head scratch: concat(64)+h1(16)

    const int lane = threadIdx.x & 31;
    const int warp = threadIdx.x >> 5;
    int b = blockIdx.x * 2 + warp;
    const bool valid = (b < B);
    if (!valid) b = B - 1;

    const int rr = lane, rz = lane + HDIM, rn = lane + 2 * HDIM;

    const float L2E  = 1.4426950408889634f;
    const float NL2E = -L2E;          // sigmoid:  s(a) = 1/(1+2^(-L2E*a))
    const float TL2E = 2.0f * L2E;    // tanh:     t(u) = 1 - 2/(2^(2*L2E*u)+1)

    // ---- W_hh rows (r,z,n for this lane): scale, convert to fp16x2 ----
    __half2 wrh[16], wzh[16], wnh[16];
    {
        const float4* pr = reinterpret_cast<const float4*>(Whh_f + rr * HDIM);
        const float4* pz = reinterpret_cast<const float4*>(Whh_f + rz * HDIM);
        const float4* pn = reinterpret_cast<const float4*>(Whh_f + rn * HDIM);
#pragma unroll
        for (int i = 0; i < 8; i++) {
            float4 a = pr[i];
            wrh[2*i]   = __floats2half2_rn(NL2E*a.x, NL2E*a.y);
            wrh[2*i+1] = __floats2half2_rn(NL2E*a.z, NL2E*a.w);
            float4 c = pz[i];
            wzh[2*i]   = __floats2half2_rn(NL2E*c.x, NL2E*c.y);
            wzh[2*i+1] = __floats2half2_rn(NL2E*c.z, NL2E*c.w);
            float4 d = pn[i];
            wnh[2*i]   = __floats2half2_rn(TL2E*d.x, TL2E*d.y);
            wnh[2*i+1] = __floats2half2_rn(TL2E*d.z, TL2E*d.w);
        }
    }
    // fp32 gate constants (biases kept out of fp16 chains)
    const u64 wrz2  = pack2(NL2E * Wih_f[rr], NL2E * Wih_f[rz]);
    const float winS = TL2E * Wih_f[rn];
    const float binS = TL2E * bih_f[rn];
    const float biasR = NL2E * (bhh_f[rr] + bih_f[rr]);
    const float biasZ = NL2E * (bhh_f[rz] + bih_f[rz]);
    const float biasN = TL2E * bhh_f[rn];
    const u64 one2  = pack2(1.0f, 1.0f);

    const float* xW = x + (size_t)b * T;

    // init h = 0 in exchange buffer parity 0 (each lane covers its own slot)
    reinterpret_cast<__half*>(xchh[warp][0])[lane] = __float2half_rn(0.0f);
    __syncwarp();

    float hs = 0.0f;   // this lane's own hidden value (kept fp32 across steps)

    auto step = [&](float xv, int rp) {
        // ---- load h (fp16, 32 values = 64B) via 4x LDS.128 ----
        const uint4* q = reinterpret_cast<const uint4*>(xchh[warp][rp]);
        uint4 qa = q[0], qb = q[1], qc = q[2], qd = q[3];
        __half2 hh[16];
        hh[0]=u2h(qa.x); hh[1]=u2h(qa.y); hh[2]=u2h(qa.z); hh[3]=u2h(qa.w);
        hh[4]=u2h(qb.x); hh[5]=u2h(qb.y); hh[6]=u2h(qb.z); hh[7]=u2h(qb.w);
        hh[8]=u2h(qc.x); hh[9]=u2h(qc.y); hh[10]=u2h(qc.z); hh[11]=u2h(qc.w);
        hh[12]=u2h(qd.x); hh[13]=u2h(qd.y); hh[14]=u2h(qd.z); hh[15]=u2h(qd.w);

        // ---- matvec: per gate, two 8-deep fp16 chains ----
        __half2 r0 = __hmul2(wrh[0], hh[0]), r1 = __hmul2(wrh[8],  hh[8]);
        __half2 z0 = __hmul2(wzh[0], hh[0]), z1 = __hmul2(wzh[8],  hh[8]);
        __half2 n0 = __hmul2(wnh[0], hh[0]), n1 = __hmul2(wnh[8],  hh[8]);
#pragma unroll
        for (int j = 1; j < 8; j++) {
            r0 = __hfma2(wrh[j],   hh[j],   r0);
            r1 = __hfma2(wrh[j+8], hh[j+8], r1);
            z0 = __hfma2(wzh[j],   hh[j],   z0);
            z1 = __hfma2(wzh[j+8], hh[j+8], z1);
            n0 = __hfma2(wnh[j],   hh[j],   n0);
            n1 = __hfma2(wnh[j+8], hh[j+8], n1);
        }
        __half2 rs = __hadd2(r0, r1);
        __half2 zs = __hadd2(z0, z1);
        __half2 ns = __hadd2(n0, n1);
        // cross-half combine + bias in fp32
        const float prR = (__low2float(rs) + __high2float(rs)) + biasR; // = -L2E*(Wr.h + br)
        const float prZ = (__low2float(zs) + __high2float(zs)) + biasZ;
        const float hn  = (__low2float(ns) + __high2float(ns)) + biasN; // = 2L2E*(Wn.h + bhn)

        // r,z = sigmoid (args pre-scaled): packed ffma2 then ex2/rcp
        float lo, hi;
        u64 pre = ffma2(pack2(xv, xv), wrz2, pack2(prR, prZ));
        unpack2(pre, lo, hi);
        u64 d_ = fadd2(pack2(ex2f(lo), ex2f(hi)), one2);
        unpack2(d_, lo, hi);
        const float r = rcpf(lo);
        const float z = rcpf(hi);
        // n = tanh(u), arg pre-scaled by 2*L2E
        const float e = ex2f(fmaf(r, hn, fmaf(xv, winS, binS)));
        const float n = fmaf(-2.0f, rcpf(e + 1.0f), 1.0f);
        // h = z*(h - n) + n
        hs = fmaf(z, hs - n, n);

        reinterpret_cast<__half*>(xchh[warp][rp ^ 1])[lane] = __float2half_rn(hs);
        __syncwarp();
    };

    // ---- main scan, 4 steps/iter, float4 x prefetch (parity 0,1,0,1) ----
    const float4* x4 = reinterpret_cast<const float4*>(xW);
    const int nIt = T >> 2;
    float4 c = x4[0];
    for (int it = 0; it < nIt; ++it) {
        int nx = (it + 1 < nIt) ? it + 1 : it;
        float4 nxt = x4[nx];
        step(c.x, 0);
        step(c.y, 1);
        step(c.z, 0);
        step(c.w, 1);
        c = nxt;
    }
    for (int t = nIt << 2; t < T; ++t) step(xW[t], t & 1);   // T%4 remainder

    // ---- backward direction: ONE step from h=0 on x[T-1] (W_hh_b unused) ----
    const float xl = xW[T - 1];
    const float rb = sigm(fmaf(xl, Wih_b[rr], bih_b[rr]) + bhh_b[rr]);
    const float zb = sigm(fmaf(xl, Wih_b[rz], bih_b[rz]) + bhh_b[rz]);
    const float nb = tanh_fast(fmaf(rb, bhh_b[rn], fmaf(xl, Wih_b[rn], bih_b[rn])));
    const float hb = (1.0f - zb) * nb;

    // ---- MLP head (per warp, own scratch, fp32) ----
    float* sc = scr[warp];
    sc[lane] = hs;
    sc[32 + lane] = hb;
    __syncwarp();

    if (lane < 16) {
        const float4* w4 = reinterpret_cast<const float4*>(W1 + lane * 64);
        float a = b1v[lane];
#pragma unroll
        for (int i = 0; i < 16; i++) {
            float4 w = w4[i];
            a = fmaf(w.x, sc[4*i],   a);
            a = fmaf(w.y, sc[4*i+1], a);
            a = fmaf(w.z, sc[4*i+2], a);
            a = fmaf(w.w, sc[4*i+3], a);
        }
        sc[64 + lane] = fmaxf(a, 0.0f);
    }
    __syncwarp();

    float v = (lane < 16) ? W2[lane] * sc[64 + lane] : 0.0f;
#pragma unroll
    for (int o = 16; o > 0; o >>= 1) v += __shfl_xor_sync(FULLMASK, v, o);

    if (lane == 0 && valid) out[b] = sigm(v + b2v[0]);
}

extern "C" void kernel_launch(void* const* d_in, const int* in_sizes, int n_in,
                              void* d_out, int out_size) {
    const float* x     = (const float*)d_in[0];
    const float* Wih_f = (const float*)d_in[1];
    const float* Whh_f = (const float*)d_in[2];
    const float* bih_f = (const float*)d_in[3];
    const float* bhh_f = (const float*)d_in[4];
    const float* Wih_b = (const float*)d_in[5];
    // d_in[6] = W_hh_b: mathematically unused (backward output at T-1 starts from h=0)
    const float* bih_b = (const float*)d_in[7];
    const float* bhh_b = (const float*)d_in[8];
    const float* W1    = (const float*)d_in[9];
    const float* b1v   = (const float*)d_in[10];
    const float* W2    = (const float*)d_in[11];
    const float* b2v   = (const float*)d_in[12];

    int B = out_size;                // output [B,1] fp32
    int T = in_sizes[0] / B;         // x is [B,T,1]

    int grid = (B + 1) / 2;          // 2 warps/block, 1 batch per warp
    gru_bidir_kernel<<<grid, 64>>>(x, Wih_f, Whh_f, bih_f, bhh_f,
                                   Wih_b, bih_b, bhh_b,
                                   W1, b1v, W2, b2v,
                                   (float*)d_out, B, T);
}

// round 10
// speedup vs baseline: 1.6157x; 1.3658x over previous
#include <cuda_runtime.h>
#include <cuda_fp16.h>

// GRU_8211977470410 — bidirectional GRU (H=32, in=1), B=2048, T=512, MLP head.
// Backward direction collapses to ONE step (scan reverse=True: ys_b[-1] = GRU(0, x[T-1])).
//
// R9: batch-packed half2 datapath.
// Two batches live in the (lo,hi) halves of every fp16x2 value. Matvec:
// HFMA2((w,w),(hA,hB)) -> both batches' dot products accumulate in one chain;
// NO cross-half combines, NO fp32 epilogue. Gates + hidden update + exchange
// all half2. Nonlinearities via tanh.approx.f16x2 (1 MUFU per gate per 2 batches);
// sigmoid as 0.5+0.5*tanh(arg) with the 0.5 pre-folded into weights/biases.
// Justified by R8 evidence: fp16 h-quantization (2.4e-4/step) -> 1e-6 final err;
// the recurrence+head is strongly error-contractive (threshold 1e-3).

#define HDIM 32
#define FULLMASK 0xffffffffu

__device__ __forceinline__ __half2 tanh_h2(__half2 a) {
    union { __half2 h; unsigned u; } in, out;
    in.h = a;
    asm("tanh.approx.f16x2 %0, %1;" : "=r"(out.u) : "r"(in.u));
    return out.h;
}
__device__ __forceinline__ __half2 u2h(unsigned v) {
    union { unsigned u; __half2 h; } c; c.u = v; return c.h;
}
__device__ __forceinline__ float sigm(float x) {
    return __fdividef(1.0f, 1.0f + __expf(-x));
}
__device__ __forceinline__ float tanh_fast(float x) {
    float e = __expf(2.0f * x);
    return 1.0f - __fdividef(2.0f, e + 1.0f);
}

__global__ void __launch_bounds__(64)
gru_bidir_kernel(const float* __restrict__ x,
                 const float* __restrict__ Wih_f, const float* __restrict__ Whh_f,
                 const float* __restrict__ bih_f, const float* __restrict__ bhh_f,
                 const float* __restrict__ Wih_b, const float* __restrict__ bih_b,
                 const float* __restrict__ bhh_b,
                 const float* __restrict__ W1, const float* __restrict__ b1v,
                 const float* __restrict__ W2, const float* __restrict__ b2v,
                 float* __restrict__ out, int B, int T)
{
    __shared__ __align__(16) __half2 xchh[2][2][32];  // [warp][parity][lane] = (hA_i, hB_i)
    __shared__ __align__(16) float scr[2][2][80];     // [warp][batch] concat(64)+h1(16)

    const int lane = threadIdx.x & 31;
    const int warp = threadIdx.x >> 5;
    int bA = blockIdx.x * 4 + warp * 2;
    int bB = bA + 1;
    const bool vA = (bA < B), vB = (bB < B);
    if (!vA) bA = B - 1;
    if (!vB) bB = B - 1;

    const int rr = lane, rz = lane + HDIM, rn = lane + 2 * HDIM;

    // ---- W_hh rows for this lane's output unit, broadcast (w,w) as half2 ----
    // r,z rows pre-scaled by 0.5 (sigmoid-via-tanh); n row unscaled.
    __half2 wr[32], wz[32], wn[32];
    {
        const float4* pr = reinterpret_cast<const float4*>(Whh_f + rr * HDIM);
        const float4* pz = reinterpret_cast<const float4*>(Whh_f + rz * HDIM);
        const float4* pn = reinterpret_cast<const float4*>(Whh_f + rn * HDIM);
#pragma unroll
        for (int i = 0; i < 8; i++) {
            float4 a = pr[i];
            wr[4*i]   = __float2half2_rn(0.5f * a.x);
            wr[4*i+1] = __float2half2_rn(0.5f * a.y);
            wr[4*i+2] = __float2half2_rn(0.5f * a.z);
            wr[4*i+3] = __float2half2_rn(0.5f * a.w);
            float4 c = pz[i];
            wz[4*i]   = __float2half2_rn(0.5f * c.x);
            wz[4*i+1] = __float2half2_rn(0.5f * c.y);
            wz[4*i+2] = __float2half2_rn(0.5f * c.z);
            wz[4*i+3] = __float2half2_rn(0.5f * c.w);
            float4 d = pn[i];
            wn[4*i]   = __float2half2_rn(d.x);
            wn[4*i+1] = __float2half2_rn(d.y);
            wn[4*i+2] = __float2half2_rn(d.z);
            wn[4*i+3] = __float2half2_rn(d.w);
        }
    }
    const __half2 wir2 = __float2half2_rn(0.5f * Wih_f[rr]);
    const __half2 wiz2 = __float2half2_rn(0.5f * Wih_f[rz]);
    const __half2 win2 = __float2half2_rn(Wih_f[rn]);
    const __half2 bin2 = __float2half2_rn(bih_f[rn]);
    const __half2 bR2  = __float2half2_rn(0.5f * (bih_f[rr] + bhh_f[rr]));
    const __half2 bZ2  = __float2half2_rn(0.5f * (bih_f[rz] + bhh_f[rz]));
    const __half2 bN2  = __float2half2_rn(bhh_f[rn]);
    const __half2 h05  = __float2half2_rn(0.5f);

    const float* xA = x + (size_t)bA * T;
    const float* xB = x + (size_t)bB * T;

    // init h = 0 in exchange buffer parity 0
    xchh[warp][0][lane] = __float2half2_rn(0.0f);
    __syncwarp();

    __half2 hs2 = __float2half2_rn(0.0f);   // this lane's hidden: (batchA, batchB)

    auto step = [&](float xav, float xbv, int rp) {
        // ---- load h: 32 half2 = 128B via 8x LDS.128 (broadcast, conflict-free) ----
        const uint4* q = reinterpret_cast<const uint4*>(xchh[warp][rp]);
        __half2 hh[32];
#pragma unroll
        for (int i = 0; i < 8; i++) {
            uint4 v = q[i];
            hh[4*i]   = u2h(v.x);
            hh[4*i+1] = u2h(v.y);
            hh[4*i+2] = u2h(v.z);
            hh[4*i+3] = u2h(v.w);
        }

        // ---- matvec: per gate 4 independent 8-deep HFMA2 chains (both batches) ----
        __half2 aR0 = __hfma2(wr[0],  hh[0],  bR2);
        __half2 aR1 = __hmul2(wr[8],  hh[8]);
        __half2 aR2 = __hmul2(wr[16], hh[16]);
        __half2 aR3 = __hmul2(wr[24], hh[24]);
        __half2 aZ0 = __hfma2(wz[0],  hh[0],  bZ2);
        __half2 aZ1 = __hmul2(wz[8],  hh[8]);
        __half2 aZ2 = __hmul2(wz[16], hh[16]);
        __half2 aZ3 = __hmul2(wz[24], hh[24]);
        __half2 aN0 = __hfma2(wn[0],  hh[0],  bN2);
        __half2 aN1 = __hmul2(wn[8],  hh[8]);
        __half2 aN2 = __hmul2(wn[16], hh[16]);
        __half2 aN3 = __hmul2(wn[24], hh[24]);
#pragma unroll
        for (int j = 1; j < 8; j++) {
            aR0 = __hfma2(wr[j],    hh[j],    aR0);
            aR1 = __hfma2(wr[j+8],  hh[j+8],  aR1);
            aR2 = __hfma2(wr[j+16], hh[j+16], aR2);
            aR3 = __hfma2(wr[j+24], hh[j+24], aR3);
            aZ0 = __hfma2(wz[j],    hh[j],    aZ0);
            aZ1 = __hfma2(wz[j+8],  hh[j+8],  aZ1);
            aZ2 = __hfma2(wz[j+16], hh[j+16], aZ2);
            aZ3 = __hfma2(wz[j+24], hh[j+24], aZ3);
            aN0 = __hfma2(wn[j],    hh[j],    aN0);
            aN1 = __hfma2(wn[j+8],  hh[j+8],  aN1);
            aN2 = __hfma2(wn[j+16], hh[j+16], aN2);
            aN3 = __hfma2(wn[j+24], hh[j+24], aN3);
        }
        const __half2 sR = __hadd2(__hadd2(aR0, aR1), __hadd2(aR2, aR3));
        const __half2 sZ = __hadd2(__hadd2(aZ0, aZ1), __hadd2(aZ2, aZ3));
        const __half2 sN = __hadd2(__hadd2(aN0, aN1), __hadd2(aN2, aN3));

        // ---- gates, both batches at once; sigmoid = 0.5 + 0.5*tanh(0.5*preact) ----
        const __half2 x2 = __floats2half2_rn(xav, xbv);
        const __half2 r2 = __hfma2(h05, tanh_h2(__hfma2(x2, wir2, sR)), h05);
        const __half2 z2 = __hfma2(h05, tanh_h2(__hfma2(x2, wiz2, sZ)), h05);
        const __half2 n2 = tanh_h2(__hfma2(r2, sN, __hfma2(x2, win2, bin2)));
        // h = z*(h - n) + n
        hs2 = __hfma2(z2, __hsub2(hs2, n2), n2);

        xchh[warp][rp ^ 1][lane] = hs2;
        __syncwarp();
    };

    // ---- main scan, 4 steps/iter, float4 x prefetch (parity 0,1,0,1) ----
    const float4* x4A = reinterpret_cast<const float4*>(xA);
    const float4* x4B = reinterpret_cast<const float4*>(xB);
    const int nIt = T >> 2;
    float4 ca = x4A[0], cb = x4B[0];
    for (int it = 0; it < nIt; ++it) {
        int nx = (it + 1 < nIt) ? it + 1 : it;
        float4 na = x4A[nx], nb = x4B[nx];
        step(ca.x, cb.x, 0);
        step(ca.y, cb.y, 1);
        step(ca.z, cb.z, 0);
        step(ca.w, cb.w, 1);
        ca = na; cb = nb;
    }
    for (int t = nIt << 2; t < T; ++t) step(xA[t], xB[t], t & 1);   // T%4 remainder

    const float hsA = __low2float(hs2);
    const float hsB = __high2float(hs2);

    // ---- backward direction: ONE step from h=0 on x[T-1], fp32 (W_hh_b unused) ----
    const float wibr = Wih_b[rr], wibz = Wih_b[rz], wibn = Wih_b[rn];
    const float bibr = bih_b[rr], bibz = bih_b[rz], bibn = bih_b[rn];
    const float bhbr = bhh_b[rr], bhbz = bhh_b[rz], bhbn = bhh_b[rn];
    const float xlA = xA[T - 1], xlB = xB[T - 1];

    const float rbA = sigm(fmaf(xlA, wibr, bibr) + bhbr);
    const float zbA = sigm(fmaf(xlA, wibz, bibz) + bhbz);
    const float nbA = tanh_fast(fmaf(rbA, bhbn, fmaf(xlA, wibn, bibn)));
    const float hbA = (1.0f - zbA) * nbA;

    const float rbB = sigm(fmaf(xlB, wibr, bibr) + bhbr);
    const float zbB = sigm(fmaf(xlB, wibz, bibz) + bhbz);
    const float nbB = tanh_fast(fmaf(rbB, bhbn, fmaf(xlB, wibn, bibn)));
    const float hbB = (1.0f - zbB) * nbB;

    // ---- MLP head (fp32), two batches per warp ----
    scr[warp][0][lane] = hsA; scr[warp][0][32 + lane] = hbA;
    scr[warp][1][lane] = hsB; scr[warp][1][32 + lane] = hbB;
    __syncwarp();

    if (lane < 16) {
        const float4* w4 = reinterpret_cast<const float4*>(W1 + lane * 64);
        float a0 = b1v[lane], a1 = a0;
        const float* s0 = scr[warp][0];
        const float* s1 = scr[warp][1];
#pragma unroll
        for (int i = 0; i < 16; i++) {
            float4 w = w4[i];
            a0 = fmaf(w.x, s0[4*i], a0);   a0 = fmaf(w.y, s0[4*i+1], a0);
            a0 = fmaf(w.z, s0[4*i+2], a0); a0 = fmaf(w.w, s0[4*i+3], a0);
            a1 = fmaf(w.x, s1[4*i], a1);   a1 = fmaf(w.y, s1[4*i+1], a1);
            a1 = fmaf(w.z, s1[4*i+2], a1); a1 = fmaf(w.w, s1[4*i+3], a1);
        }
        scr[warp][0][64 + lane] = fmaxf(a0, 0.0f);
        scr[warp][1][64 + lane] = fmaxf(a1, 0.0f);
    }
    __syncwarp();

    float v0 = (lane < 16) ? W2[lane] * scr[warp][0][64 + lane] : 0.0f;
    float v1 = (lane < 16) ? W2[lane] * scr[warp][1][64 + lane] : 0.0f;
#pragma unroll
    for (int o = 16; o > 0; o >>= 1) {
        v0 += __shfl_xor_sync(FULLMASK, v0, o);
        v1 += __shfl_xor_sync(FULLMASK, v1, o);
    }
    if (lane == 0) {
        float bb2 = b2v[0];
        if (vA) out[bA] = sigm(v0 + bb2);
        if (vB) out[bB] = sigm(v1 + bb2);
    }
}

extern "C" void kernel_launch(void* const* d_in, const int* in_sizes, int n_in,
                              void* d_out, int out_size) {
    const float* x     = (const float*)d_in[0];
    const float* Wih_f = (const float*)d_in[1];
    const float* Whh_f = (const float*)d_in[2];
    const float* bih_f = (const float*)d_in[3];
    const float* bhh_f = (const float*)d_in[4];
    const float* Wih_b = (const float*)d_in[5];
    // d_in[6] = W_hh_b: mathematically unused (backward output at T-1 starts from h=0)
    const float* bih_b = (const float*)d_in[7];
    const float* bhh_b = (const float*)d_in[8];
    const float* W1    = (const float*)d_in[9];
    const float* b1v   = (const float*)d_in[10];
    const float* W2    = (const float*)d_in[11];
    const float* b2v   = (const float*)d_in[12];

    int B = out_size;                // output [B,1] fp32
    int T = in_sizes[0] / B;         // x is [B,T,1]

    int grid = (B + 3) / 4;          // 2 warps/block, 2 batches per warp
    gru_bidir_kernel<<<grid, 64>>>(x, Wih_f, Whh_f, bih_f, bhh_f,
                                   Wih_b, bih_b, bhh_b,
                                   W1, b1v, W2, b2v,
                                   (float*)d_out, B, T);
}

// round 12
// speedup vs baseline: 2.2124x; 1.3694x over previous
#include <cuda_runtime.h>

// GRU_8211977470410 — bidirectional GRU (H=32, in=1), B=2048, T=512, MLP head.
// Backward direction collapses to ONE step (scan reverse=True: ys_b[-1] = GRU(0, x[T-1])).
//
// R10: int8 matvec via dp4a (4 MACs per issue slot vs HFMA2's 2).
// W_hh rows quantized to s8 with per-row scale; h exchanged as s8 (scale 127,
// |h|<1 guaranteed by GRU convexity); recurrence state hs and ALL gate math in
// fp32 (tanh.approx.f32). s32 dot accumulation is exact; dequant = I2F + FFMA.
// 2048 warps x 1 batch (1024 blocks x 64 thr, single wave, 3.46 warps/SMSP —
// the ~84%-utilization regime measured in R7). Sigmoid = 0.5 + 0.5*tanh(pre/2)
// with the 0.5 folded into scales/biases.

#define HDIM 32
#define FULLMASK 0xffffffffu
typedef unsigned int u32;

__device__ __forceinline__ int dp4a(u32 a, u32 b, int c) {
    int d;
    asm("dp4a.s32.s32 %0, %1, %2, %3;" : "=r"(d) : "r"(a), "r"(b), "r"(c));
    return d;
}
__device__ __forceinline__ float tanhap(float x) {
    float r; asm("tanh.approx.f32 %0, %1;" : "=f"(r) : "f"(x)); return r;
}
__device__ __forceinline__ float sigm(float x) {
    return __fdividef(1.0f, 1.0f + __expf(-x));
}
__device__ __forceinline__ float tanh_fast(float x) {
    float e = __expf(2.0f * x);
    return 1.0f - __fdividef(2.0f, e + 1.0f);
}
__device__ __forceinline__ u32 packs8(int a, int b, int c, int d) {
    return (u32)(a & 0xFF) | ((u32)(b & 0xFF) << 8) |
           ((u32)(c & 0xFF) << 16) | ((u32)(d & 0xFF) << 24);
}

__global__ void __launch_bounds__(64)
gru_bidir_kernel(const float* __restrict__ x,
                 const float* __restrict__ Wih_f, const float* __restrict__ Whh_f,
                 const float* __restrict__ bih_f, const float* __restrict__ bhh_f,
                 const float* __restrict__ Wih_b, const float* __restrict__ bih_b,
                 const float* __restrict__ bhh_b,
                 const float* __restrict__ W1, const float* __restrict__ b1v,
                 const float* __restrict__ W2, const float* __restrict__ b2v,
                 float* __restrict__ out, int B, int T)
{
    __shared__ __align__(16) u32 xq[2][2][8];   // [warp][parity][8 words] h as s8
    __shared__ __align__(16) float scr[2][80];  // [warp] head scratch: concat(64)+h1(16)

    const int lane = threadIdx.x & 31;
    const int warp = threadIdx.x >> 5;
    int b = blockIdx.x * 2 + warp;
    const bool valid = (b < B);
    if (!valid) b = B - 1;

    const int rr = lane, rz = lane + HDIM, rn = lane + 2 * HDIM;

    // ---- quantize this lane's three W_hh rows to s8 (per-row scale) ----
    u32 wqR[8], wqZ[8], wqN[8];
    float kR, kZ, kN;   // dequant scales (0.5 folded into r,z for sigmoid-via-tanh)
    {
        const int rows[3] = { rr, rz, rn };
        u32* dst[3] = { wqR, wqZ, wqN };
        float kk[3];
#pragma unroll
        for (int g = 0; g < 3; g++) {
            const float* p = Whh_f + rows[g] * HDIM;
            float amax = 1e-12f;
#pragma unroll
            for (int j = 0; j < HDIM; j++) amax = fmaxf(amax, fabsf(p[j]));
            const float qs = 127.0f / amax;
#pragma unroll
            for (int i = 0; i < 8; i++) {
                int q0 = __float2int_rn(p[4*i]     * qs);
                int q1 = __float2int_rn(p[4*i + 1] * qs);
                int q2 = __float2int_rn(p[4*i + 2] * qs);
                int q3 = __float2int_rn(p[4*i + 3] * qs);
                dst[g][i] = packs8(q0, q1, q2, q3);
            }
            kk[g] = amax / (127.0f * 127.0f);   // w*h == idot * kk
        }
        kR = 0.5f * kk[0];
        kZ = 0.5f * kk[1];
        kN = kk[2];
    }
    // gate constants (0.5 folded for r,z sigmoid-via-tanh)
    const float wirH = 0.5f * Wih_f[rr], bRc = 0.5f * (bih_f[rr] + bhh_f[rr]);
    const float wizH = 0.5f * Wih_f[rz], bZc = 0.5f * (bih_f[rz] + bhh_f[rz]);
    const float winS = Wih_f[rn], binS = bih_f[rn], bhnS = bhh_f[rn];

    const float* xW = x + (size_t)b * T;

    // init h = 0 in exchange buffer parity 0 (one byte per lane)
    reinterpret_cast<char*>(xq[warp][0])[lane] = 0;
    __syncwarp();

    float hs = 0.0f;   // this lane's hidden value, fp32 across steps

    auto step = [&](float xv, int rp) {
        // ---- load h (32 x s8 = 32B) via 2x LDS.128 ----
        const uint4* q = reinterpret_cast<const uint4*>(xq[warp][rp]);
        uint4 qa = q[0], qb = q[1];
        u32 hw[8] = { qa.x, qa.y, qa.z, qa.w, qb.x, qb.y, qb.z, qb.w };

        // ---- matvec: 3 gates x 8 dp4a (s32 exact accumulation) ----
        int iR = 0, iZ = 0, iN = 0;
#pragma unroll
        for (int k = 0; k < 8; k++) {
            iR = dp4a(wqR[k], hw[k], iR);
            iZ = dp4a(wqZ[k], hw[k], iZ);
            iN = dp4a(wqN[k], hw[k], iN);
        }

        // ---- gates in fp32; sigmoid = 0.5 + 0.5*tanh(pre/2) ----
        const float preR = fmaf((float)iR, kR, fmaf(xv, wirH, bRc));
        const float preZ = fmaf((float)iZ, kZ, fmaf(xv, wizH, bZc));
        const float r = fmaf(0.5f, tanhap(preR), 0.5f);
        const float z = fmaf(0.5f, tanhap(preZ), 0.5f);
        const float inner = fmaf((float)iN, kN, bhnS);
        const float n = tanhap(fmaf(r, inner, fmaf(xv, winS, binS)));
        // h = z*(h - n) + n
        hs = fmaf(z, hs - n, n);

        // ---- quantize + exchange (|h| < 1 so |q| <= 127) ----
        const int qh = __float2int_rn(hs * 127.0f);
        reinterpret_cast<char*>(xq[warp][rp ^ 1])[lane] = (char)qh;
        __syncwarp();
    };

    // ---- main scan, 4 steps/iter, float4 x prefetch (parity 0,1,0,1) ----
    const float4* x4 = reinterpret_cast<const float4*>(xW);
    const int nIt = T >> 2;
    float4 c = x4[0];
    for (int it = 0; it < nIt; ++it) {
        int nx = (it + 1 < nIt) ? it + 1 : it;
        float4 nxt = x4[nx];
        step(c.x, 0);
        step(c.y, 1);
        step(c.z, 0);
        step(c.w, 1);
        c = nxt;
    }
    for (int t = nIt << 2; t < T; ++t) step(xW[t], t & 1);   // T%4 remainder

    // ---- backward direction: ONE step from h=0 on x[T-1], fp32 (W_hh_b unused) ----
    const float xl = xW[T - 1];
    const float rb = sigm(fmaf(xl, Wih_b[rr], bih_b[rr]) + bhh_b[rr]);
    const float zb = sigm(fmaf(xl, Wih_b[rz], bih_b[rz]) + bhh_b[rz]);
    const float nb = tanh_fast(fmaf(rb, bhh_b[rn], fmaf(xl, Wih_b[rn], bih_b[rn])));
    const float hb = (1.0f - zb) * nb;

    // ---- MLP head (fp32, per warp) ----
    float* sc = scr[warp];
    sc[lane] = hs;
    sc[32 + lane] = hb;
    __syncwarp();

    if (lane < 16) {
        const float4* w4 = reinterpret_cast<const float4*>(W1 + lane * 64);
        float a = b1v[lane];
#pragma unroll
        for (int i = 0; i < 16; i++) {
            float4 w = w4[i];
            a = fmaf(w.x, sc[4*i],   a);
            a = fmaf(w.y, sc[4*i+1], a);
            a = fmaf(w.z, sc[4*i+2], a);
            a = fmaf(w.w, sc[4*i+3], a);
        }
        sc[64 + lane] = fmaxf(a, 0.0f);
    }
    __syncwarp();

    float v = (lane < 16) ? W2[lane] * sc[64 + lane] : 0.0f;
#pragma unroll
    for (int o = 16; o > 0; o >>= 1) v += __shfl_xor_sync(FULLMASK, v, o);

    if (lane == 0 && valid) out[b] = sigm(v + b2v[0]);
}

extern "C" void kernel_launch(void* const* d_in, const int* in_sizes, int n_in,
                              void* d_out, int out_size) {
    const float* x     = (const float*)d_in[0];
    const float* Wih_f = (const float*)d_in[1];
    const float* Whh_f = (const float*)d_in[2];
    const float* bih_f = (const float*)d_in[3];
    const float* bhh_f = (const float*)d_in[4];
    const float* Wih_b = (const float*)d_in[5];
    // d_in[6] = W_hh_b: mathematically unused (backward output at T-1 starts from h=0)
    const float* bih_b = (const float*)d_in[7];
    const float* bhh_b = (const float*)d_in[8];
    const float* W1    = (const float*)d_in[9];
    const float* b1v   = (const float*)d_in[10];
    const float* W2    = (const float*)d_in[11];
    const float* b2v   = (const float*)d_in[12];

    int B = out_size;                // output [B,1] fp32
    int T = in_sizes[0] / B;         // x is [B,T,1]

    int grid = (B + 1) / 2;          // 2 warps/block, 1 batch per warp, single wave
    gru_bidir_kernel<<<grid, 64>>>(x, Wih_f, Whh_f, bih_f, bhh_f,
                                   Wih_b, bih_b, bhh_b,
                                   W1, b1v, W2, b2v,
                                   (float*)d_out, B, T);
}

// round 13
// speedup vs baseline: 2.2905x; 1.0353x over previous
#include <cuda_runtime.h>

// GRU_8211977470410 — bidirectional GRU (H=32, in=1), B=2048, T=512, MLP head.
// Backward direction collapses to ONE step (scan reverse=True: ys_b[-1] = GRU(0, x[T-1])).
//
// R12: dp4a int8 matvec (R10) + serial-path surgery:
//  - magic-number int<->float conversions (IADD/FADD, lat 4, vs I2F/F2I lat ~20);
//    f32->s8 store is FFMA + STS.U8 of the low mantissa byte (zero extra ops)
//  - dp4a chains split 2x4-deep, IADD3 join on the (idle) ALU pipe
//  - 2 batches per warp: one syncwarp/loop-overhead per 2 batches, two
//    independent chains per warp for stall hiding. 512 blocks x 64 thr.
// Gate math fp32 with tanh.approx.f32; sigmoid = 0.5 + 0.5*tanh(pre/2).

#define HDIM 32
#define FULLMASK 0xffffffffu
typedef unsigned int u32;

#define MAGIC_F 12582912.0f          // 1.5 * 2^23
#define MAGIC_I 0x4B400000           // bit pattern of 12582912.0f

__device__ __forceinline__ int dp4a(u32 a, u32 b, int c) {
    int d;
    asm("dp4a.s32.s32 %0, %1, %2, %3;" : "=r"(d) : "r"(a), "r"(b), "r"(c));
    return d;
}
__device__ __forceinline__ float i2f_magic(int i) {
    // exact for |i| < 2^22
    return __uint_as_float((u32)(MAGIC_I + i)) - MAGIC_F;
}
__device__ __forceinline__ float tanhap(float x) {
    float r; asm("tanh.approx.f32 %0, %1;" : "=f"(r) : "f"(x)); return r;
}
__device__ __forceinline__ float sigm(float x) {
    return __fdividef(1.0f, 1.0f + __expf(-x));
}
__device__ __forceinline__ float tanh_fast(float x) {
    float e = __expf(2.0f * x);
    return 1.0f - __fdividef(2.0f, e + 1.0f);
}
__device__ __forceinline__ u32 packs8(int a, int b, int c, int d) {
    return (u32)(a & 0xFF) | ((u32)(b & 0xFF) << 8) |
           ((u32)(c & 0xFF) << 16) | ((u32)(d & 0xFF) << 24);
}

__global__ void __launch_bounds__(64)
gru_bidir_kernel(const float* __restrict__ x,
                 const float* __restrict__ Wih_f, const float* __restrict__ Whh_f,
                 const float* __restrict__ bih_f, const float* __restrict__ bhh_f,
                 const float* __restrict__ Wih_b, const float* __restrict__ bih_b,
                 const float* __restrict__ bhh_b,
                 const float* __restrict__ W1, const float* __restrict__ b1v,
                 const float* __restrict__ W2, const float* __restrict__ b2v,
                 float* __restrict__ out, int B, int T)
{
    // [warp][parity][batch(2) x 8 words] : h as s8, 64B per parity
    __shared__ __align__(16) u32 xq[2][2][16];
    __shared__ __align__(16) float scr[2][2][80];  // [warp][batch] concat(64)+h1(16)

    const int lane = threadIdx.x & 31;
    const int warp = threadIdx.x >> 5;
    int bA = blockIdx.x * 4 + warp * 2;
    int bB = bA + 1;
    const bool vA = (bA < B), vB = (bB < B);
    if (!vA) bA = B - 1;
    if (!vB) bB = B - 1;

    const int rr = lane, rz = lane + HDIM, rn = lane + 2 * HDIM;

    // ---- quantize this lane's three W_hh rows to s8 (per-row scale) ----
    u32 wqR[8], wqZ[8], wqN[8];
    float kR, kZ, kN;
    {
        const int rows[3] = { rr, rz, rn };
        u32* dst[3] = { wqR, wqZ, wqN };
        float kk[3];
#pragma unroll
        for (int g = 0; g < 3; g++) {
            const float* p = Whh_f + rows[g] * HDIM;
            float amax = 1e-12f;
#pragma unroll
            for (int j = 0; j < HDIM; j++) amax = fmaxf(amax, fabsf(p[j]));
            const float qs = 127.0f / amax;
#pragma unroll
            for (int i = 0; i < 8; i++) {
                dst[g][i] = packs8(__float2int_rn(p[4*i]     * qs),
                                   __float2int_rn(p[4*i + 1] * qs),
                                   __float2int_rn(p[4*i + 2] * qs),
                                   __float2int_rn(p[4*i + 3] * qs));
            }
            kk[g] = amax / (127.0f * 127.0f);
        }
        kR = 0.5f * kk[0];   // 0.5 folded: sigmoid = 0.5 + 0.5*tanh(pre/2)
        kZ = 0.5f * kk[1];
        kN = kk[2];
    }
    const float wirH = 0.5f * Wih_f[rr], bRc = 0.5f * (bih_f[rr] + bhh_f[rr]);
    const float wizH = 0.5f * Wih_f[rz], bZc = 0.5f * (bih_f[rz] + bhh_f[rz]);
    const float winS = Wih_f[rn], binS = bih_f[rn], bhnS = bhh_f[rn];

    const float* xA = x + (size_t)bA * T;
    const float* xB = x + (size_t)bB * T;

    // init h = 0 in parity-0 buffer (one byte per lane per batch)
    {
        char* p0 = reinterpret_cast<char*>(xq[warp][0]);
        p0[lane] = 0;
        p0[32 + lane] = 0;
    }
    __syncwarp();

    float hsA = 0.0f, hsB = 0.0f;

    auto step = [&](float xav, float xbv, int rp) {
        // ---- load h for both batches: 64B via 4x LDS.128 (broadcast) ----
        const uint4* q = reinterpret_cast<const uint4*>(xq[warp][rp]);
        uint4 a0 = q[0], a1 = q[1];            // batch A words 0..7
        uint4 b0 = q[2], b1 = q[3];            // batch B words 0..7
        u32 hA[8] = { a0.x, a0.y, a0.z, a0.w, a1.x, a1.y, a1.z, a1.w };
        u32 hB[8] = { b0.x, b0.y, b0.z, b0.w, b1.x, b1.y, b1.z, b1.w };

        // ---- matvec: per batch per gate, 2 independent 4-deep dp4a chains ----
        int rA0 = 0, rA1 = 0, zA0 = 0, zA1 = 0, nA0 = 0, nA1 = 0;
        int rB0 = 0, rB1 = 0, zB0 = 0, zB1 = 0, nB0 = 0, nB1 = 0;
#pragma unroll
        for (int k = 0; k < 4; k++) {
            rA0 = dp4a(wqR[k], hA[k], rA0);  rA1 = dp4a(wqR[k+4], hA[k+4], rA1);
            zA0 = dp4a(wqZ[k], hA[k], zA0);  zA1 = dp4a(wqZ[k+4], hA[k+4], zA1);
            nA0 = dp4a(wqN[k], hA[k], nA0);  nA1 = dp4a(wqN[k+4], hA[k+4], nA1);
            rB0 = dp4a(wqR[k], hB[k], rB0);  rB1 = dp4a(wqR[k+4], hB[k+4], rB1);
            zB0 = dp4a(wqZ[k], hB[k], zB0);  zB1 = dp4a(wqZ[k+4], hB[k+4], zB1);
            nB0 = dp4a(wqN[k], hB[k], nB0);  nB1 = dp4a(wqN[k+4], hB[k+4], nB1);
        }

        // ---- gates fp32 (magic int->float), both batches ----
        const float fRA = i2f_magic(rA0 + rA1);
        const float fZA = i2f_magic(zA0 + zA1);
        const float fNA = i2f_magic(nA0 + nA1);
        const float fRB = i2f_magic(rB0 + rB1);
        const float fZB = i2f_magic(zB0 + zB1);
        const float fNB = i2f_magic(nB0 + nB1);

        const float rA = tanhap(fmaf(fRA, kR, fmaf(xav, wirH, bRc)));
        const float zA = tanhap(fmaf(fZA, kZ, fmaf(xav, wizH, bZc)));
        const float rB = tanhap(fmaf(fRB, kR, fmaf(xbv, wirH, bRc)));
        const float zB = tanhap(fmaf(fZB, kZ, fmaf(xbv, wizH, bZc)));
        // r,z in [−1,1] tanh form: σ = 0.5 + 0.5*t
        const float innA = fmaf(fNA, kN, bhnS);
        const float innB = fmaf(fNB, kN, bhnS);
        const float nA = tanhap(fmaf(fmaf(0.5f, rA, 0.5f), innA, fmaf(xav, winS, binS)));
        const float nB = tanhap(fmaf(fmaf(0.5f, rB, 0.5f), innB, fmaf(xbv, winS, binS)));
        // h = z*(h-n)+n with z = 0.5+0.5*t  =>  h = 0.5*t*(h-n) + 0.5*(h-n) + n
        const float dA = hsA - nA;
        const float dB = hsB - nB;
        hsA = fmaf(0.5f * zA, dA, fmaf(0.5f, dA, nA));
        hsB = fmaf(0.5f * zB, dB, fmaf(0.5f, dB, nB));

        // ---- quantize via magic FFMA; store low mantissa byte (STS.U8) ----
        const u32 qhA = __float_as_uint(fmaf(hsA, 127.0f, MAGIC_F));
        const u32 qhB = __float_as_uint(fmaf(hsB, 127.0f, MAGIC_F));
        char* pw = reinterpret_cast<char*>(xq[warp][rp ^ 1]);
        pw[lane]      = (char)(qhA & 0xFF);
        pw[32 + lane] = (char)(qhB & 0xFF);
        __syncwarp();
    };

    // ---- main scan, 4 steps/iter, float4 x prefetch (parity 0,1,0,1) ----
    const float4* x4A = reinterpret_cast<const float4*>(xA);
    const float4* x4B = reinterpret_cast<const float4*>(xB);
    const int nIt = T >> 2;
    float4 ca = x4A[0], cb = x4B[0];
    for (int it = 0; it < nIt; ++it) {
        int nx = (it + 1 < nIt) ? it + 1 : it;
        float4 na = x4A[nx], nb = x4B[nx];
        step(ca.x, cb.x, 0);
        step(ca.y, cb.y, 1);
        step(ca.z, cb.z, 0);
        step(ca.w, cb.w, 1);
        ca = na; cb = nb;
    }
    for (int t = nIt << 2; t < T; ++t) step(xA[t], xB[t], t & 1);   // T%4 remainder

    // ---- backward direction: ONE step from h=0 on x[T-1], fp32 (W_hh_b unused) ----
    const float wibr = Wih_b[rr], wibz = Wih_b[rz], wibn = Wih_b[rn];
    const float bibr = bih_b[rr], bibz = bih_b[rz], bibn = bih_b[rn];
    const float bhbr = bhh_b[rr], bhbz = bhh_b[rz], bhbn = bhh_b[rn];
    const float xlA = xA[T - 1], xlB = xB[T - 1];

    const float rbA = sigm(fmaf(xlA, wibr, bibr) + bhbr);
    const float zbA = sigm(fmaf(xlA, wibz, bibz) + bhbz);
    const float nbA = tanh_fast(fmaf(rbA, bhbn, fmaf(xlA, wibn, bibn)));
    const float hbA = (1.0f - zbA) * nbA;

    const float rbB = sigm(fmaf(xlB, wibr, bibr) + bhbr);
    const float zbB = sigm(fmaf(xlB, wibz, bibz) + bhbz);
    const float nbB = tanh_fast(fmaf(rbB, bhbn, fmaf(xlB, wibn, bibn)));
    const float hbB = (1.0f - zbB) * nbB;

    // ---- MLP head (fp32), two batches per warp ----
    scr[warp][0][lane] = hsA; scr[warp][0][32 + lane] = hbA;
    scr[warp][1][lane] = hsB; scr[warp][1][32 + lane] = hbB;
    __syncwarp();

    if (lane < 16) {
        const float4* w4 = reinterpret_cast<const float4*>(W1 + lane * 64);
        float a0 = b1v[lane], a1 = a0;
        const float* s0 = scr[warp][0];
        const float* s1 = scr[warp][1];
#pragma unroll
        for (int i = 0; i < 16; i++) {
            float4 w = w4[i];
            a0 = fmaf(w.x, s0[4*i], a0);   a0 = fmaf(w.y, s0[4*i+1], a0);
            a0 = fmaf(w.z, s0[4*i+2], a0); a0 = fmaf(w.w, s0[4*i+3], a0);
            a1 = fmaf(w.x, s1[4*i], a1);   a1 = fmaf(w.y, s1[4*i+1], a1);
            a1 = fmaf(w.z, s1[4*i+2], a1); a1 = fmaf(w.w, s1[4*i+3], a1);
        }
        scr[warp][0][64 + lane] = fmaxf(a0, 0.0f);
        scr[warp][1][64 + lane] = fmaxf(a1, 0.0f);
    }
    __syncwarp();

    float v0 = (lane < 16) ? W2[lane] * scr[warp][0][64 + lane] : 0.0f;
    float v1 = (lane < 16) ? W2[lane] * scr[warp][1][64 + lane] : 0.0f;
#pragma unroll
    for (int o = 16; o > 0; o >>= 1) {
        v0 += __shfl_xor_sync(FULLMASK, v0, o);
        v1 += __shfl_xor_sync(FULLMASK, v1, o);
    }
    if (lane == 0) {
        float bb2 = b2v[0];
        if (vA) out[bA] = sigm(v0 + bb2);
        if (vB) out[bB] = sigm(v1 + bb2);
    }
}

extern "C" void kernel_launch(void* const* d_in, const int* in_sizes, int n_in,
                              void* d_out, int out_size) {
    const float* x     = (const float*)d_in[0];
    const float* Wih_f = (const float*)d_in[1];
    const float* Whh_f = (const float*)d_in[2];
    const float* bih_f = (const float*)d_in[3];
    const float* bhh_f = (const float*)d_in[4];
    const float* Wih_b = (const float*)d_in[5];
    // d_in[6] = W_hh_b: mathematically unused (backward output at T-1 starts from h=0)
    const float* bih_b = (const float*)d_in[7];
    const float* bhh_b = (const float*)d_in[8];
    const float* W1    = (const float*)d_in[9];
    const float* b1v   = (const float*)d_in[10];
    const float* W2    = (const float*)d_in[11];
    const float* b2v   = (const float*)d_in[12];

    int B = out_size;                // output [B,1] fp32
    int T = in_sizes[0] / B;         // x is [B,T,1]

    int grid = (B + 3) / 4;          // 2 warps/block, 2 batches per warp
    gru_bidir_kernel<<<grid, 64>>>(x, Wih_f, Whh_f, bih_f, bhh_f,
                                   Wih_b, bih_b, bhh_b,
                                   W1, b1v, W2, b2v,
                                   (float*)d_out, B, T);
}